// round 9
// baseline (speedup 1.0000x reference)
#include <cuda_runtime.h>
#include <math.h>

// Problem constants
#define B      16384
#define IN     64
#define HID    128
#define E      64
#define NMAP   1000
#define TILE_M 64
#define NBLK   64                       // binning blocks (B/256)
#define MAX_TILES (B / TILE_M + E)      // 320
#define MLP_THREADS 256

// Scratch (device globals; no allocation allowed)
__device__ int g_e[B];
__device__ int g_hist[NBLK * E];        // per-block histogram rows
__device__ int g_expOff[E];
__device__ int g_counts[E];
__device__ int g_bucket[B];
__device__ int g_tileExpert[MAX_TILES];
__device__ int g_tileIdx[MAX_TILES];
__device__ int g_numTiles;
__device__ int g_bar1;                  // inter-phase arrive counter
__device__ int g_bar2;                  // completion counter (for reset)

// ---------------------------------------------------------------------------
// K1: fused binning. grid=64 (all resident) x 256 threads.
// Phase A: expert ids + per-block histogram. Device-wide barrier.
// Phase B: per-block prefix scan from g_hist + counting-sort scatter;
//          block 0 also emits the tile map. Barrier counters self-reset.
__global__ __launch_bounds__(256) void bin_kernel(const int* __restrict__ num32,
                                                  const int* __restrict__ c32) {
    __shared__ int hs[E];
    __shared__ int s_stride;
    __shared__ int basev[E];
    __shared__ int s_wsum[2], s_wsum2[2];
    int t = threadIdx.x, b = blockIdx.x;
    int lane = t & 31, warp = t >> 5;

    // ---- Phase A: histogram
    if (t == 0) {
        int is64 = 1;
        for (int j = 1; j < 64; j += 2)
            if (c32[j] != 0) { is64 = 0; break; }
        s_stride = is64 ? 2 : 1;
    }
    if (t < E) hs[t] = 0;
    __syncthreads();
    int stride = s_stride;
    int i = b * 256 + t;
    int n = num32[(size_t)i * stride];
    n = n < 0 ? 0 : (n >= NMAP ? NMAP - 1 : n);
    int e = c32[(size_t)n * stride];
    e = e < 0 ? 0 : (e >= E ? E - 1 : e);
    g_e[i] = e;
    atomicAdd(&hs[e], 1);
    __syncthreads();
    if (t < E) g_hist[b * E + t] = hs[t];
    __threadfence();

    // ---- Device-wide barrier (all 64 CTAs resident; deterministic reset below)
    if (t == 0) {
        atomicAdd(&g_bar1, 1);
        while (atomicAdd(&g_bar1, 0) < NBLK) { }
    }
    __syncthreads();

    // ---- Phase B: scans + scatter
    int tot = 0, pre = 0, exclC = 0, exclT = 0, nt = 0;
    if (t < E) {
        hs[t] = 0;   // reuse as local rank counter
        #pragma unroll 4
        for (int bb = 0; bb < NBLK; bb++) {
            int v = g_hist[bb * E + t];
            tot += v;
            if (bb < b) pre += v;
        }
        nt = (tot + TILE_M - 1) / TILE_M;
        int s1 = tot, s2 = nt;
        #pragma unroll
        for (int off = 1; off < 32; off <<= 1) {
            int n1 = __shfl_up_sync(0xFFFFFFFFu, s1, off);
            int n2 = __shfl_up_sync(0xFFFFFFFFu, s2, off);
            if (lane >= off) { s1 += n1; s2 += n2; }
        }
        exclC = s1 - tot;
        exclT = s2 - nt;
        if (lane == 31) { s_wsum[warp] = s1; s_wsum2[warp] = s2; }
    }
    __syncthreads();
    if (t < E) {
        int addC = (warp == 1) ? s_wsum[0]  : 0;
        int addT = (warp == 1) ? s_wsum2[0] : 0;
        int eOff = exclC + addC;
        basev[t] = eOff + pre;
        if (b == 0) {
            g_counts[t] = tot;
            g_expOff[t] = eOff;
            int t0 = exclT + addT;
            for (int j = 0; j < nt; j++) {
                g_tileExpert[t0 + j] = t;
                g_tileIdx[t0 + j]    = j;
            }
            if (t == E - 1) g_numTiles = t0 + nt;
        }
    }
    __syncthreads();
    int r = atomicAdd(&hs[e], 1);
    g_bucket[basev[e] + r] = i;

    // ---- Completion + deterministic counter reset for graph replay
    __syncthreads();
    if (t == 0) {
        int d = atomicAdd(&g_bar2, 1);
        if (d == NBLK - 1) { g_bar1 = 0; g_bar2 = 0; }
    }
}

// ---------------------------------------------------------------------------
// K2: per-tile fused MLP. CTA = (expert, 64-sample tile), 256 threads (8 warps).
// tx = tid&15 -> 8 hidden units; ty = tid>>4 -> 4 samples. 4x8 register tile.
// Static SMEM 48KB; grid ~260 real tiles -> ~14 warps/SM achieved.
__global__ __launch_bounds__(MLP_THREADS) void mlp_kernel(
    const float* __restrict__ x,
    const float* __restrict__ W1,
    const float* __restrict__ b1,
    const float* __restrict__ W2,
    const float* __restrict__ b2,
    float* __restrict__ out)
{
    __shared__ float sW[IN * HID];      // [k*128 + h]  32KB
    __shared__ float sX[IN * TILE_M];   // [k*64 + m]   16KB

    int tile = blockIdx.x;
    if (tile >= g_numTiles) return;

    int e    = g_tileExpert[tile];
    int ti   = g_tileIdx[tile];
    int cnt  = g_counts[e];
    int base = g_expOff[e] + ti * TILE_M;
    int mvalid = cnt - ti * TILE_M;
    if (mvalid > TILE_M) mvalid = TILE_M;

    // ---- Load W1[e]: 2048 float4 across 256 threads (8 each)
    {
        const float4* Wg  = (const float4*)(W1 + (size_t)e * IN * HID);
        float4*       Ws4 = (float4*)sW;
        #pragma unroll
        for (int i = threadIdx.x; i < (IN * HID) / 4; i += MLP_THREADS)
            Ws4[i] = Wg[i];
    }

    // ---- Load X tile transposed: 4 threads/row, 16 k each
    {
        int m  = threadIdx.x >> 2;               // 0..63
        int kq = (threadIdx.x & 3) * 16;
        int mc = m < mvalid ? m : (mvalid - 1);  // clamp (outputs guarded)
        int gidx = g_bucket[base + mc];
        const float4* xr = (const float4*)(x + (size_t)gidx * IN + kq);
        #pragma unroll
        for (int q = 0; q < 4; q++) {
            float4 v = xr[q];
            int k0 = kq + q * 4;
            sX[(k0 + 0) * TILE_M + m] = v.x;
            sX[(k0 + 1) * TILE_M + m] = v.y;
            sX[(k0 + 2) * TILE_M + m] = v.z;
            sX[(k0 + 3) * TILE_M + m] = v.w;
        }
    }
    __syncthreads();

    int tx = threadIdx.x & 15;   // hid group (8 units)
    int ty = threadIdx.x >> 4;   // sample group (4 samples)

    float acc[4][8];
    #pragma unroll
    for (int mm = 0; mm < 4; mm++)
        #pragma unroll
        for (int j = 0; j < 8; j++)
            acc[mm][j] = 0.0f;

    // ---- Mainloop: K=64; per k: 3 LDS.128 + 32 FFMA
    #pragma unroll 8
    for (int k = 0; k < IN; k++) {
        float4 a4 = *(const float4*)&sX[k * TILE_M + ty * 4];
        float4 w0 = *(const float4*)&sW[k * HID + tx * 8];
        float4 w1 = *(const float4*)&sW[k * HID + tx * 8 + 4];
        float a[4]  = {a4.x, a4.y, a4.z, a4.w};
        float bb[8] = {w0.x, w0.y, w0.z, w0.w, w1.x, w1.y, w1.z, w1.w};
        #pragma unroll
        for (int mm = 0; mm < 4; mm++)
            #pragma unroll
            for (int j = 0; j < 8; j++)
                acc[mm][j] = fmaf(a[mm], bb[j], acc[mm][j]);
    }

    // ---- Epilogue: +b1, relu, partial dot with w2, reduce over 16 tx groups
    float b1r[8], w2r[8];
    {
        const float* b1e = b1 + (size_t)e * HID + tx * 8;
        const float* w2e = W2 + (size_t)e * HID + tx * 8;   // OUT=1
        #pragma unroll
        for (int j = 0; j < 8; j++) { b1r[j] = b1e[j]; w2r[j] = w2e[j]; }
    }

    __syncthreads();   // done reading sX/sW; reuse sX as reduction buffer
    // reduction buffer: sX[row*17 + tx], rows 0..63 (padded stride 17)

    #pragma unroll
    for (int mm = 0; mm < 4; mm++) {
        float p = 0.0f;
        #pragma unroll
        for (int j = 0; j < 8; j++) {
            float h = acc[mm][j] + b1r[j];
            h = h > 0.0f ? h : 0.0f;
            p = fmaf(h, w2r[j], p);
        }
        sX[(ty * 4 + mm) * 17 + tx] = p;
    }
    __syncthreads();

    if (threadIdx.x < TILE_M) {
        int m = threadIdx.x;
        if (m < mvalid) {
            float s = 0.0f;
            #pragma unroll
            for (int t = 0; t < 16; t++) s += sX[m * 17 + t];
            float y = s + b2[e];
            int gidx = g_bucket[base + m];
            out[gidx] = 1.0f / (1.0f + expf(-y));
        }
    }
}

// ---------------------------------------------------------------------------
extern "C" void kernel_launch(void* const* d_in, const int* in_sizes, int n_in,
                              void* d_out, int out_size) {
    const float* x     = (const float*)d_in[0];
    const int*   num32 = (const int*)d_in[1];
    const int*   c32   = (const int*)d_in[2];
    const float* W1    = (const float*)d_in[3];
    const float* b1    = (const float*)d_in[4];
    const float* W2    = (const float*)d_in[5];
    const float* b2    = (const float*)d_in[6];
    float*       out   = (float*)d_out;

    static bool attr_set = false;
    if (!attr_set) {
        cudaFuncSetAttribute(mlp_kernel,
                             cudaFuncAttributePreferredSharedMemoryCarveout, 100);
        attr_set = true;
    }

    bin_kernel<<<NBLK, 256>>>(num32, c32);
    mlp_kernel<<<MAX_TILES, MLP_THREADS>>>(x, W1, b1, W2, b2, out);
}

// round 11
// speedup vs baseline: 1.2452x; 1.2452x over previous
#include <cuda_runtime.h>
#include <math.h>

// Problem constants
#define B      16384
#define IN     64
#define HID    128
#define E      64
#define NMAP   1000
#define TILE_M 64
#define NBLK   64                       // binning blocks (B/256)
#define MAX_TILES (B / TILE_M + E)      // 320
#define MLP_THREADS 128

// Scratch (device globals; no allocation allowed)
__device__ int g_e[B];
__device__ int g_hist[NBLK * E];        // per-block histogram rows
__device__ int g_expOff[E];
__device__ int g_counts[E];
__device__ int g_bucket[B];
__device__ int g_tileExpert[MAX_TILES];
__device__ int g_tileIdx[MAX_TILES];
__device__ int g_numTiles;
__device__ int g_bar1;                  // inter-phase arrive counter
__device__ int g_bar2;                  // completion counter (for reset)

// packed f32x2 helpers (Blackwell; FFMA2 only reachable via PTX)
__device__ __forceinline__ unsigned long long ffma2(unsigned long long a,
                                                    unsigned long long b,
                                                    unsigned long long c) {
    unsigned long long d;
    asm("fma.rn.f32x2 %0, %1, %2, %3;" : "=l"(d) : "l"(a), "l"(b), "l"(c));
    return d;
}
__device__ __forceinline__ unsigned long long pack2(float v) {
    unsigned long long r;
    asm("mov.b64 %0, {%1, %1};" : "=l"(r) : "f"(v));
    return r;
}
__device__ __forceinline__ float2 unpack2(unsigned long long v) {
    float2 f;
    asm("mov.b64 {%0, %1}, %2;" : "=f"(f.x), "=f"(f.y) : "l"(v));
    return f;
}

// ---------------------------------------------------------------------------
// K1: fused binning. grid=64 (all resident) x 256 threads.
// Phase A: expert ids + per-block histogram. Device-wide barrier.
// Phase B: per-block prefix scan from g_hist + counting-sort scatter;
//          block 0 also emits the tile map. Barrier counters self-reset.
__global__ __launch_bounds__(256) void bin_kernel(const int* __restrict__ num32,
                                                  const int* __restrict__ c32) {
    __shared__ int hs[E];
    __shared__ int s_stride;
    __shared__ int basev[E];
    __shared__ int s_wsum[2], s_wsum2[2];
    int t = threadIdx.x, b = blockIdx.x;
    int lane = t & 31, warp = t >> 5;

    // ---- Phase A: histogram
    if (t == 0) {
        int is64 = 1;
        for (int j = 1; j < 64; j += 2)
            if (c32[j] != 0) { is64 = 0; break; }
        s_stride = is64 ? 2 : 1;
    }
    if (t < E) hs[t] = 0;
    __syncthreads();
    int stride = s_stride;
    int i = b * 256 + t;
    int n = num32[(size_t)i * stride];
    n = n < 0 ? 0 : (n >= NMAP ? NMAP - 1 : n);
    int e = c32[(size_t)n * stride];
    e = e < 0 ? 0 : (e >= E ? E - 1 : e);
    g_e[i] = e;
    atomicAdd(&hs[e], 1);
    __syncthreads();
    if (t < E) g_hist[b * E + t] = hs[t];
    __threadfence();

    // ---- Device-wide barrier (all 64 CTAs resident; deterministic reset below)
    if (t == 0) {
        atomicAdd(&g_bar1, 1);
        while (atomicAdd(&g_bar1, 0) < NBLK) { }
    }
    __syncthreads();

    // ---- Phase B: scans + scatter
    int tot = 0, pre = 0, exclC = 0, exclT = 0, nt = 0;
    if (t < E) {
        hs[t] = 0;   // reuse as local rank counter
        #pragma unroll 4
        for (int bb = 0; bb < NBLK; bb++) {
            int v = g_hist[bb * E + t];
            tot += v;
            if (bb < b) pre += v;
        }
        nt = (tot + TILE_M - 1) / TILE_M;
        int s1 = tot, s2 = nt;
        #pragma unroll
        for (int off = 1; off < 32; off <<= 1) {
            int n1 = __shfl_up_sync(0xFFFFFFFFu, s1, off);
            int n2 = __shfl_up_sync(0xFFFFFFFFu, s2, off);
            if (lane >= off) { s1 += n1; s2 += n2; }
        }
        exclC = s1 - tot;
        exclT = s2 - nt;
        if (lane == 31) { s_wsum[warp] = s1; s_wsum2[warp] = s2; }
    }
    __syncthreads();
    if (t < E) {
        int addC = (warp == 1) ? s_wsum[0]  : 0;
        int addT = (warp == 1) ? s_wsum2[0] : 0;
        int eOff = exclC + addC;
        basev[t] = eOff + pre;
        if (b == 0) {
            g_counts[t] = tot;
            g_expOff[t] = eOff;
            int t0 = exclT + addT;
            for (int j = 0; j < nt; j++) {
                g_tileExpert[t0 + j] = t;
                g_tileIdx[t0 + j]    = j;
            }
            if (t == E - 1) g_numTiles = t0 + nt;
        }
    }
    __syncthreads();
    int r = atomicAdd(&hs[e], 1);
    g_bucket[basev[e] + r] = i;

    // ---- Completion + deterministic counter reset for graph replay
    __syncthreads();
    if (t == 0) {
        int d = atomicAdd(&g_bar2, 1);
        if (d == NBLK - 1) { g_bar1 = 0; g_bar2 = 0; }
    }
}

// ---------------------------------------------------------------------------
// K2: per-tile fused MLP. CTA = (expert, 64-sample tile), 128 threads (R8 shape).
// tx = tid&15 -> 8 hidden units (4 f32x2 pairs); ty = tid>>4 -> 8 samples.
// Mainloop uses packed fma.rn.f32x2: 32 FFMA2/k instead of 64 FFMA/k.
__global__ __launch_bounds__(MLP_THREADS) void mlp_kernel(
    const float* __restrict__ x,
    const float* __restrict__ W1,
    const float* __restrict__ b1,
    const float* __restrict__ W2,
    const float* __restrict__ b2,
    float* __restrict__ out)
{
    __shared__ float sW[IN * HID];      // [k*128 + h]  32KB
    __shared__ float sX[IN * TILE_M];   // [k*64 + m]   16KB

    int tile = blockIdx.x;
    if (tile >= g_numTiles) return;

    int e    = g_tileExpert[tile];
    int ti   = g_tileIdx[tile];
    int cnt  = g_counts[e];
    int base = g_expOff[e] + ti * TILE_M;
    int mvalid = cnt - ti * TILE_M;
    if (mvalid > TILE_M) mvalid = TILE_M;

    // ---- Load W1[e]: 2048 float4 across 128 threads (16 each)
    {
        const float4* Wg  = (const float4*)(W1 + (size_t)e * IN * HID);
        float4*       Ws4 = (float4*)sW;
        #pragma unroll
        for (int i = threadIdx.x; i < (IN * HID) / 4; i += MLP_THREADS)
            Ws4[i] = Wg[i];
    }

    // ---- Load X tile transposed: 2 threads/row, 32-float half-rows
    {
        int m  = threadIdx.x >> 1;               // 0..63
        int kq = (threadIdx.x & 1) * 32;
        int mc = m < mvalid ? m : (mvalid - 1);  // clamp (outputs guarded)
        int gidx = g_bucket[base + mc];
        const float4* xr = (const float4*)(x + (size_t)gidx * IN + kq);
        #pragma unroll
        for (int q = 0; q < 8; q++) {
            float4 v = xr[q];
            int k0 = kq + q * 4;
            sX[(k0 + 0) * TILE_M + m] = v.x;
            sX[(k0 + 1) * TILE_M + m] = v.y;
            sX[(k0 + 2) * TILE_M + m] = v.z;
            sX[(k0 + 3) * TILE_M + m] = v.w;
        }
    }
    __syncthreads();

    int tx = threadIdx.x & 15;   // hid group (8 units = 4 packed pairs)
    int ty = threadIdx.x >> 4;   // sample group (8 samples)

    unsigned long long acc[8][4];
    #pragma unroll
    for (int mm = 0; mm < 8; mm++)
        #pragma unroll
        for (int jp = 0; jp < 4; jp++)
            acc[mm][jp] = 0ULL;

    // ---- Mainloop: K=64; per k: 4 LDS.128 + 8 packs (ALU) + 32 FFMA2 (FMA)
    #pragma unroll 4
    for (int k = 0; k < IN; k++) {
        float4 a0 = *(const float4*)&sX[k * TILE_M + ty * 8];
        float4 a1 = *(const float4*)&sX[k * TILE_M + ty * 8 + 4];
        ulonglong2 w0 = *(const ulonglong2*)&sW[k * HID + tx * 8];
        ulonglong2 w1 = *(const ulonglong2*)&sW[k * HID + tx * 8 + 4];
        unsigned long long ap[8];
        ap[0] = pack2(a0.x); ap[1] = pack2(a0.y);
        ap[2] = pack2(a0.z); ap[3] = pack2(a0.w);
        ap[4] = pack2(a1.x); ap[5] = pack2(a1.y);
        ap[6] = pack2(a1.z); ap[7] = pack2(a1.w);
        unsigned long long wp[4] = {w0.x, w0.y, w1.x, w1.y};
        #pragma unroll
        for (int mm = 0; mm < 8; mm++)
            #pragma unroll
            for (int jp = 0; jp < 4; jp++)
                acc[mm][jp] = ffma2(ap[mm], wp[jp], acc[mm][jp]);
    }

    // ---- Epilogue: +b1, relu, partial dot with w2, reduce over 16 tx groups
    float b1r[8], w2r[8];
    {
        const float* b1e = b1 + (size_t)e * HID + tx * 8;
        const float* w2e = W2 + (size_t)e * HID + tx * 8;   // OUT=1
        #pragma unroll
        for (int j = 0; j < 8; j++) { b1r[j] = b1e[j]; w2r[j] = w2e[j]; }
    }

    __syncthreads();   // done reading sX/sW; reuse sX as reduction buffer
    // reduction buffer: sX[row*17 + tx], rows 0..63 (padded stride 17)

    #pragma unroll
    for (int mm = 0; mm < 8; mm++) {
        float p = 0.0f;
        #pragma unroll
        for (int jp = 0; jp < 4; jp++) {
            float2 f = unpack2(acc[mm][jp]);
            float h0 = f.x + b1r[2 * jp];
            float h1 = f.y + b1r[2 * jp + 1];
            h0 = h0 > 0.0f ? h0 : 0.0f;
            h1 = h1 > 0.0f ? h1 : 0.0f;
            p = fmaf(h0, w2r[2 * jp], p);
            p = fmaf(h1, w2r[2 * jp + 1], p);
        }
        sX[(ty * 8 + mm) * 17 + tx] = p;
    }
    __syncthreads();

    if (threadIdx.x < TILE_M) {
        int m = threadIdx.x;
        if (m < mvalid) {
            float s = 0.0f;
            #pragma unroll
            for (int t = 0; t < 16; t++) s += sX[m * 17 + t];
            float y = s + b2[e];
            int gidx = g_bucket[base + m];
            out[gidx] = 1.0f / (1.0f + expf(-y));
        }
    }
}

// ---------------------------------------------------------------------------
extern "C" void kernel_launch(void* const* d_in, const int* in_sizes, int n_in,
                              void* d_out, int out_size) {
    const float* x     = (const float*)d_in[0];
    const int*   num32 = (const int*)d_in[1];
    const int*   c32   = (const int*)d_in[2];
    const float* W1    = (const float*)d_in[3];
    const float* b1    = (const float*)d_in[4];
    const float* W2    = (const float*)d_in[5];
    const float* b2    = (const float*)d_in[6];
    float*       out   = (float*)d_out;

    static bool attr_set = false;
    if (!attr_set) {
        cudaFuncSetAttribute(mlp_kernel,
                             cudaFuncAttributePreferredSharedMemoryCarveout, 100);
        attr_set = true;
    }

    bin_kernel<<<NBLK, 256>>>(num32, c32);
    mlp_kernel<<<MAX_TILES, MLP_THREADS>>>(x, W1, b1, W2, b2, out);
}

// round 13
// speedup vs baseline: 1.4728x; 1.1828x over previous
#include <cuda_runtime.h>
#include <math.h>

// Problem constants
#define B      16384
#define IN     64
#define HID    128
#define E      64
#define NMAP   1000
#define TILE_M 64
#define NBLK   64                       // binning blocks (B/256)
#define MAX_TILES (B / TILE_M + E)      // 320
#define MLP_THREADS 128
#define PAD    68                        // padded k-stride (bank = 4g+t = lane)

// SMEM layout (floats)
#define SXB_OFF 0
#define SXR_OFF (TILE_M * PAD)                  // 4352
#define SWB_OFF (2 * TILE_M * PAD)              // 8704
#define SWR_OFF (2 * TILE_M * PAD + HID * PAD)  // 17408
#define SMEM_FLOATS (2 * TILE_M * PAD + 2 * HID * PAD)   // 26112
#define SMEM_BYTES  (SMEM_FLOATS * 4)                     // 104448

// Scratch (device globals; no allocation allowed)
__device__ int g_e[B];
__device__ int g_hist[NBLK * E];        // per-block histogram rows
__device__ int g_expOff[E];
__device__ int g_counts[E];
__device__ int g_bucket[B];
__device__ int g_tileExpert[MAX_TILES];
__device__ int g_tileIdx[MAX_TILES];
__device__ int g_numTiles;
__device__ int g_bar1;                  // inter-phase arrive counter
__device__ int g_bar2;                  // completion counter (for reset)

// ---- tf32 helpers -----------------------------------------------------------
__device__ __forceinline__ unsigned f2tf32(float v) {
    unsigned u;
    asm("cvt.rna.tf32.f32 %0, %1;" : "=r"(u) : "f"(v));
    return u;
}
// D += A(tf32) * B(tf32), m16n8k8, A row-major, B col-major
__device__ __forceinline__ void mma_tf32(float c[4],
                                         unsigned a0, unsigned a1, unsigned a2, unsigned a3,
                                         unsigned b0, unsigned b1) {
    asm("mma.sync.aligned.m16n8k8.row.col.f32.tf32.tf32.f32 "
        "{%0,%1,%2,%3}, {%4,%5,%6,%7}, {%8,%9}, {%0,%1,%2,%3};"
        : "+f"(c[0]), "+f"(c[1]), "+f"(c[2]), "+f"(c[3])
        : "r"(a0), "r"(a1), "r"(a2), "r"(a3), "r"(b0), "r"(b1));
}

// ---------------------------------------------------------------------------
// K1: fused binning (unchanged from R8). grid=64 x 256.
__global__ __launch_bounds__(256) void bin_kernel(const int* __restrict__ num32,
                                                  const int* __restrict__ c32) {
    __shared__ int hs[E];
    __shared__ int s_stride;
    __shared__ int basev[E];
    __shared__ int s_wsum[2], s_wsum2[2];
    int t = threadIdx.x, b = blockIdx.x;
    int lane = t & 31, warp = t >> 5;

    if (t == 0) {
        int is64 = 1;
        for (int j = 1; j < 64; j += 2)
            if (c32[j] != 0) { is64 = 0; break; }
        s_stride = is64 ? 2 : 1;
    }
    if (t < E) hs[t] = 0;
    __syncthreads();
    int stride = s_stride;
    int i = b * 256 + t;
    int n = num32[(size_t)i * stride];
    n = n < 0 ? 0 : (n >= NMAP ? NMAP - 1 : n);
    int e = c32[(size_t)n * stride];
    e = e < 0 ? 0 : (e >= E ? E - 1 : e);
    g_e[i] = e;
    atomicAdd(&hs[e], 1);
    __syncthreads();
    if (t < E) g_hist[b * E + t] = hs[t];
    __threadfence();

    if (t == 0) {
        atomicAdd(&g_bar1, 1);
        while (atomicAdd(&g_bar1, 0) < NBLK) { }
    }
    __syncthreads();

    int tot = 0, pre = 0, exclC = 0, exclT = 0, nt = 0;
    if (t < E) {
        hs[t] = 0;
        #pragma unroll 4
        for (int bb = 0; bb < NBLK; bb++) {
            int v = g_hist[bb * E + t];
            tot += v;
            if (bb < b) pre += v;
        }
        nt = (tot + TILE_M - 1) / TILE_M;
        int s1 = tot, s2 = nt;
        #pragma unroll
        for (int off = 1; off < 32; off <<= 1) {
            int n1 = __shfl_up_sync(0xFFFFFFFFu, s1, off);
            int n2 = __shfl_up_sync(0xFFFFFFFFu, s2, off);
            if (lane >= off) { s1 += n1; s2 += n2; }
        }
        exclC = s1 - tot;
        exclT = s2 - nt;
        if (lane == 31) { s_wsum[warp] = s1; s_wsum2[warp] = s2; }
    }
    __syncthreads();
    if (t < E) {
        int addC = (warp == 1) ? s_wsum[0]  : 0;
        int addT = (warp == 1) ? s_wsum2[0] : 0;
        int eOff = exclC + addC;
        basev[t] = eOff + pre;
        if (b == 0) {
            g_counts[t] = tot;
            g_expOff[t] = eOff;
            int t0 = exclT + addT;
            for (int j = 0; j < nt; j++) {
                g_tileExpert[t0 + j] = t;
                g_tileIdx[t0 + j]    = j;
            }
            if (t == E - 1) g_numTiles = t0 + nt;
        }
    }
    __syncthreads();
    int r = atomicAdd(&hs[e], 1);
    g_bucket[basev[e] + r] = i;

    __syncthreads();
    if (t == 0) {
        int d = atomicAdd(&g_bar2, 1);
        if (d == NBLK - 1) { g_bar1 = 0; g_bar2 = 0; }
    }
}

// ---------------------------------------------------------------------------
// K2: per-tile fused MLP via tf32 mma.sync with 3xTF32 split.
// CTA = (expert, 64-sample tile), 128 threads (4 warps).
// Warp w owns hidden cols [w*32, w*32+32). m16n8k8 tiles: 4 M-tiles x 4 N-tiles.
// SMEM: Xb/Xr [64 m][68], Wb/Wr [128 h][68] (transposed, tf32 big + residual).
__global__ __launch_bounds__(MLP_THREADS) void mlp_kernel(
    const float* __restrict__ x,
    const float* __restrict__ W1,
    const float* __restrict__ b1,
    const float* __restrict__ W2,
    const float* __restrict__ b2,
    float* __restrict__ out)
{
    extern __shared__ float smem[];
    float* sXb = smem + SXB_OFF;
    float* sXr = smem + SXR_OFF;
    float* sWb = smem + SWB_OFF;
    float* sWr = smem + SWR_OFF;

    int tile = blockIdx.x;
    if (tile >= g_numTiles) return;

    int e    = g_tileExpert[tile];
    int ti   = g_tileIdx[tile];
    int cnt  = g_counts[e];
    int base = g_expOff[e] + ti * TILE_M;
    int mvalid = cnt - ti * TILE_M;
    if (mvalid > TILE_M) mvalid = TILE_M;

    // ---- Load + split W1[e] transposed: sW[h][k], coalesced gmem reads
    {
        const float* W1e = W1 + (size_t)e * IN * HID;
        #pragma unroll
        for (int i = threadIdx.x; i < IN * HID; i += MLP_THREADS) {
            int k = i >> 7, h = i & 127;
            float v = W1e[i];
            unsigned bu = f2tf32(v);
            float big = __uint_as_float(bu);
            float r = v - big;
            sWb[h * PAD + k] = big;
            sWr[h * PAD + k] = __uint_as_float(f2tf32(r));
        }
    }

    // ---- Load + split X tile: sX[m][k], 2 threads/row
    {
        int m  = threadIdx.x >> 1;               // 0..63
        int kq = (threadIdx.x & 1) * 32;
        int mc = m < mvalid ? m : (mvalid - 1);  // clamp (outputs guarded)
        int gidx = g_bucket[base + mc];
        const float4* xr = (const float4*)(x + (size_t)gidx * IN + kq);
        #pragma unroll
        for (int q = 0; q < 8; q++) {
            float4 v = xr[q];
            int k0 = kq + q * 4;
            float vv[4] = {v.x, v.y, v.z, v.w};
            #pragma unroll
            for (int cmp = 0; cmp < 4; cmp++) {
                float val = vv[cmp];
                unsigned bu = f2tf32(val);
                float big = __uint_as_float(bu);
                float r = val - big;
                sXb[m * PAD + k0 + cmp] = big;
                sXr[m * PAD + k0 + cmp] = __uint_as_float(f2tf32(r));
            }
        }
    }
    __syncthreads();

    int lane = threadIdx.x & 31;
    int w    = threadIdx.x >> 5;     // warp -> N block [w*32, w*32+32)
    int g    = lane >> 2;            // group id 0..7
    int t4   = lane & 3;             // thread in group 0..3

    float C[4][4][4];                // [mtile][ntile][frag]
    #pragma unroll
    for (int mt = 0; mt < 4; mt++)
        #pragma unroll
        for (int nt = 0; nt < 4; nt++)
            #pragma unroll
            for (int f = 0; f < 4; f++)
                C[mt][nt][f] = 0.0f;

    // ---- Mainloop: 8 k-steps; per step 48 frag loads + 48 MMAs
    #pragma unroll
    for (int ks = 0; ks < 8; ks++) {
        unsigned Ab[4][4], Ar[4][4], Bb[4][2], Br[4][2];
        int kb = ks * 8 + t4;
        #pragma unroll
        for (int mt = 0; mt < 4; mt++) {
            int r0 = (mt * 16 + g) * PAD + kb;
            Ab[mt][0] = __float_as_uint(sXb[r0]);
            Ab[mt][1] = __float_as_uint(sXb[r0 + 8 * PAD]);
            Ab[mt][2] = __float_as_uint(sXb[r0 + 4]);
            Ab[mt][3] = __float_as_uint(sXb[r0 + 8 * PAD + 4]);
            Ar[mt][0] = __float_as_uint(sXr[r0]);
            Ar[mt][1] = __float_as_uint(sXr[r0 + 8 * PAD]);
            Ar[mt][2] = __float_as_uint(sXr[r0 + 4]);
            Ar[mt][3] = __float_as_uint(sXr[r0 + 8 * PAD + 4]);
        }
        #pragma unroll
        for (int nt = 0; nt < 4; nt++) {
            int c0 = (w * 32 + nt * 8 + g) * PAD + kb;
            Bb[nt][0] = __float_as_uint(sWb[c0]);
            Bb[nt][1] = __float_as_uint(sWb[c0 + 4]);
            Br[nt][0] = __float_as_uint(sWr[c0]);
            Br[nt][1] = __float_as_uint(sWr[c0 + 4]);
        }
        #pragma unroll
        for (int mt = 0; mt < 4; mt++)
            #pragma unroll
            for (int nt = 0; nt < 4; nt++) {
                mma_tf32(C[mt][nt], Ab[mt][0], Ab[mt][1], Ab[mt][2], Ab[mt][3],
                         Bb[nt][0], Bb[nt][1]);
                mma_tf32(C[mt][nt], Ar[mt][0], Ar[mt][1], Ar[mt][2], Ar[mt][3],
                         Bb[nt][0], Bb[nt][1]);
                mma_tf32(C[mt][nt], Ab[mt][0], Ab[mt][1], Ab[mt][2], Ab[mt][3],
                         Br[nt][0], Br[nt][1]);
            }
    }

    // ---- Epilogue: +b1, relu, dot w2 (per-thread 8 cols/row), quad reduce
    float b1p[4][2], w2p[4][2];
    #pragma unroll
    for (int nt = 0; nt < 4; nt++) {
        int col = w * 32 + nt * 8 + t4 * 2;
        float2 bb = *(const float2*)(b1 + (size_t)e * HID + col);
        float2 ww = *(const float2*)(W2 + (size_t)e * HID + col);
        b1p[nt][0] = bb.x; b1p[nt][1] = bb.y;
        w2p[nt][0] = ww.x; w2p[nt][1] = ww.y;
    }

    __syncthreads();   // all warps done reading sXb; reuse as reduction buffer
    float* red = sXb;  // red[m*4 + w], 256 floats

    #pragma unroll
    for (int mt = 0; mt < 4; mt++) {
        float s0 = 0.0f, s1 = 0.0f;
        #pragma unroll
        for (int nt = 0; nt < 4; nt++) {
            #pragma unroll
            for (int cc = 0; cc < 2; cc++) {
                float h0 = C[mt][nt][cc]     + b1p[nt][cc];
                float h1 = C[mt][nt][2 + cc] + b1p[nt][cc];
                h0 = h0 > 0.0f ? h0 : 0.0f;
                h1 = h1 > 0.0f ? h1 : 0.0f;
                s0 = fmaf(h0, w2p[nt][cc], s0);
                s1 = fmaf(h1, w2p[nt][cc], s1);
            }
        }
        // reduce over the 4 threads of the quad (t4 = 0..3)
        s0 += __shfl_xor_sync(0xFFFFFFFFu, s0, 1);
        s0 += __shfl_xor_sync(0xFFFFFFFFu, s0, 2);
        s1 += __shfl_xor_sync(0xFFFFFFFFu, s1, 1);
        s1 += __shfl_xor_sync(0xFFFFFFFFu, s1, 2);
        if (t4 == 0) {
            red[(mt * 16 + g) * 4 + w]     = s0;
            red[(mt * 16 + 8 + g) * 4 + w] = s1;
        }
    }
    __syncthreads();

    if (threadIdx.x < TILE_M) {
        int m = threadIdx.x;
        if (m < mvalid) {
            float s = red[m * 4] + red[m * 4 + 1] + red[m * 4 + 2] + red[m * 4 + 3];
            float y = s + b2[e];
            int gidx = g_bucket[base + m];
            out[gidx] = 1.0f / (1.0f + expf(-y));
        }
    }
}

// ---------------------------------------------------------------------------
extern "C" void kernel_launch(void* const* d_in, const int* in_sizes, int n_in,
                              void* d_out, int out_size) {
    const float* x     = (const float*)d_in[0];
    const int*   num32 = (const int*)d_in[1];
    const int*   c32   = (const int*)d_in[2];
    const float* W1    = (const float*)d_in[3];
    const float* b1    = (const float*)d_in[4];
    const float* W2    = (const float*)d_in[5];
    const float* b2    = (const float*)d_in[6];
    float*       out   = (float*)d_out;

    static bool attr_set = false;
    if (!attr_set) {
        cudaFuncSetAttribute(mlp_kernel,
                             cudaFuncAttributeMaxDynamicSharedMemorySize,
                             SMEM_BYTES);
        cudaFuncSetAttribute(mlp_kernel,
                             cudaFuncAttributePreferredSharedMemoryCarveout, 100);
        attr_set = true;
    }

    bin_kernel<<<NBLK, 256>>>(num32, c32);
    mlp_kernel<<<MAX_TILES, MLP_THREADS, SMEM_BYTES>>>(x, W1, b1, W2, b2, out);
}

// round 14
// speedup vs baseline: 1.4863x; 1.0091x over previous
#include <cuda_runtime.h>
#include <math.h>

// Problem constants
#define B      16384
#define IN     64
#define HID    128
#define E      64
#define NMAP   1000
#define TILE_M 64
#define NBLK   64                       // binning blocks (B/256)
#define MAX_TILES (B / TILE_M + E)      // 320
#define MLP_THREADS 256
#define PAD    68                        // padded k-stride (bank = 4g+t = lane)

// SMEM layout (floats)
#define SXB_OFF 0
#define SXR_OFF (TILE_M * PAD)                  // 4352
#define SWB_OFF (2 * TILE_M * PAD)              // 8704
#define SWR_OFF (2 * TILE_M * PAD + HID * PAD)  // 17408
#define SMEM_FLOATS (2 * TILE_M * PAD + 2 * HID * PAD)   // 26112
#define SMEM_BYTES  (SMEM_FLOATS * 4)                     // 104448

// Scratch (device globals; no allocation allowed)
__device__ int g_e[B];
__device__ int g_hist[NBLK * E];        // per-block histogram rows
__device__ int g_expOff[E];
__device__ int g_counts[E];
__device__ int g_bucket[B];
__device__ int g_tileExpert[MAX_TILES];
__device__ int g_tileIdx[MAX_TILES];
__device__ int g_numTiles;
__device__ int g_bar1;                  // inter-phase arrive counter
__device__ int g_bar2;                  // completion counter (for reset)

// ---- tf32 helpers -----------------------------------------------------------
__device__ __forceinline__ unsigned f2tf32(float v) {
    unsigned u;
    asm("cvt.rna.tf32.f32 %0, %1;" : "=r"(u) : "f"(v));
    return u;
}
// D += A(tf32) * B(tf32), m16n8k8, A row-major, B col-major
__device__ __forceinline__ void mma_tf32(float c[4],
                                         unsigned a0, unsigned a1, unsigned a2, unsigned a3,
                                         unsigned b0, unsigned b1) {
    asm("mma.sync.aligned.m16n8k8.row.col.f32.tf32.tf32.f32 "
        "{%0,%1,%2,%3}, {%4,%5,%6,%7}, {%8,%9}, {%0,%1,%2,%3};"
        : "+f"(c[0]), "+f"(c[1]), "+f"(c[2]), "+f"(c[3])
        : "r"(a0), "r"(a1), "r"(a2), "r"(a3), "r"(b0), "r"(b1));
}

// ---------------------------------------------------------------------------
// K1: fused binning (unchanged). grid=64 x 256.
__global__ __launch_bounds__(256) void bin_kernel(const int* __restrict__ num32,
                                                  const int* __restrict__ c32) {
    __shared__ int hs[E];
    __shared__ int s_stride;
    __shared__ int basev[E];
    __shared__ int s_wsum[2], s_wsum2[2];
    int t = threadIdx.x, b = blockIdx.x;
    int lane = t & 31, warp = t >> 5;

    if (t == 0) {
        int is64 = 1;
        for (int j = 1; j < 64; j += 2)
            if (c32[j] != 0) { is64 = 0; break; }
        s_stride = is64 ? 2 : 1;
    }
    if (t < E) hs[t] = 0;
    __syncthreads();
    int stride = s_stride;
    int i = b * 256 + t;
    int n = num32[(size_t)i * stride];
    n = n < 0 ? 0 : (n >= NMAP ? NMAP - 1 : n);
    int e = c32[(size_t)n * stride];
    e = e < 0 ? 0 : (e >= E ? E - 1 : e);
    g_e[i] = e;
    atomicAdd(&hs[e], 1);
    __syncthreads();
    if (t < E) g_hist[b * E + t] = hs[t];
    __threadfence();

    if (t == 0) {
        atomicAdd(&g_bar1, 1);
        while (atomicAdd(&g_bar1, 0) < NBLK) { }
    }
    __syncthreads();

    int tot = 0, pre = 0, exclC = 0, exclT = 0, nt = 0;
    if (t < E) {
        hs[t] = 0;
        #pragma unroll 4
        for (int bb = 0; bb < NBLK; bb++) {
            int v = g_hist[bb * E + t];
            tot += v;
            if (bb < b) pre += v;
        }
        nt = (tot + TILE_M - 1) / TILE_M;
        int s1 = tot, s2 = nt;
        #pragma unroll
        for (int off = 1; off < 32; off <<= 1) {
            int n1 = __shfl_up_sync(0xFFFFFFFFu, s1, off);
            int n2 = __shfl_up_sync(0xFFFFFFFFu, s2, off);
            if (lane >= off) { s1 += n1; s2 += n2; }
        }
        exclC = s1 - tot;
        exclT = s2 - nt;
        if (lane == 31) { s_wsum[warp] = s1; s_wsum2[warp] = s2; }
    }
    __syncthreads();
    if (t < E) {
        int addC = (warp == 1) ? s_wsum[0]  : 0;
        int addT = (warp == 1) ? s_wsum2[0] : 0;
        int eOff = exclC + addC;
        basev[t] = eOff + pre;
        if (b == 0) {
            g_counts[t] = tot;
            g_expOff[t] = eOff;
            int t0 = exclT + addT;
            for (int j = 0; j < nt; j++) {
                g_tileExpert[t0 + j] = t;
                g_tileIdx[t0 + j]    = j;
            }
            if (t == E - 1) g_numTiles = t0 + nt;
        }
    }
    __syncthreads();
    int r = atomicAdd(&hs[e], 1);
    g_bucket[basev[e] + r] = i;

    __syncthreads();
    if (t == 0) {
        int d = atomicAdd(&g_bar2, 1);
        if (d == NBLK - 1) { g_bar1 = 0; g_bar2 = 0; }
    }
}

// ---------------------------------------------------------------------------
// K2: per-tile fused MLP via tf32 mma.sync with 3xTF32 split.
// CTA = (expert, 64-sample tile), 256 threads (8 warps).
// Warp w owns hidden cols [w*16, w*16+16): 2 n-tiles of 8.
// m16n8k8 tiles: 4 M-tiles x 2 N-tiles per warp.
__global__ __launch_bounds__(MLP_THREADS) void mlp_kernel(
    const float* __restrict__ x,
    const float* __restrict__ W1,
    const float* __restrict__ b1,
    const float* __restrict__ W2,
    const float* __restrict__ b2,
    float* __restrict__ out)
{
    extern __shared__ float smem[];
    float* sXb = smem + SXB_OFF;
    float* sXr = smem + SXR_OFF;
    float* sWb = smem + SWB_OFF;
    float* sWr = smem + SWR_OFF;

    int tile = blockIdx.x;
    if (tile >= g_numTiles) return;

    int e    = g_tileExpert[tile];
    int ti   = g_tileIdx[tile];
    int cnt  = g_counts[e];
    int base = g_expOff[e] + ti * TILE_M;
    int mvalid = cnt - ti * TILE_M;
    if (mvalid > TILE_M) mvalid = TILE_M;

    // ---- Load + split W1[e] transposed: sW[h][k], coalesced gmem reads
    {
        const float* W1e = W1 + (size_t)e * IN * HID;
        #pragma unroll
        for (int i = threadIdx.x; i < IN * HID; i += MLP_THREADS) {
            int k = i >> 7, h = i & 127;
            float v = W1e[i];
            unsigned bu = f2tf32(v);
            float big = __uint_as_float(bu);
            float r = v - big;
            sWb[h * PAD + k] = big;
            sWr[h * PAD + k] = __uint_as_float(f2tf32(r));
        }
    }

    // ---- Load + split X tile: sX[m][k], 4 threads/row
    {
        int m  = threadIdx.x >> 2;               // 0..63
        int kq = (threadIdx.x & 3) * 16;
        int mc = m < mvalid ? m : (mvalid - 1);  // clamp (outputs guarded)
        int gidx = g_bucket[base + mc];
        const float4* xr = (const float4*)(x + (size_t)gidx * IN + kq);
        #pragma unroll
        for (int q = 0; q < 4; q++) {
            float4 v = xr[q];
            int k0 = kq + q * 4;
            float vv[4] = {v.x, v.y, v.z, v.w};
            #pragma unroll
            for (int cmp = 0; cmp < 4; cmp++) {
                float val = vv[cmp];
                unsigned bu = f2tf32(val);
                float big = __uint_as_float(bu);
                float r = val - big;
                sXb[m * PAD + k0 + cmp] = big;
                sXr[m * PAD + k0 + cmp] = __uint_as_float(f2tf32(r));
            }
        }
    }
    __syncthreads();

    int lane = threadIdx.x & 31;
    int w    = threadIdx.x >> 5;     // warp -> N block [w*16, w*16+16)
    int g    = lane >> 2;            // group id 0..7
    int t4   = lane & 3;             // thread in group 0..3

    float C[4][2][4];                // [mtile][ntile][frag]
    #pragma unroll
    for (int mt = 0; mt < 4; mt++)
        #pragma unroll
        for (int nt = 0; nt < 2; nt++)
            #pragma unroll
            for (int f = 0; f < 4; f++)
                C[mt][nt][f] = 0.0f;

    // ---- Mainloop: 8 k-steps; per step 40 frag loads + 24 MMAs per warp
    #pragma unroll
    for (int ks = 0; ks < 8; ks++) {
        unsigned Ab[4][4], Ar[4][4], Bb[2][2], Br[2][2];
        int kb = ks * 8 + t4;
        #pragma unroll
        for (int mt = 0; mt < 4; mt++) {
            int r0 = (mt * 16 + g) * PAD + kb;
            Ab[mt][0] = __float_as_uint(sXb[r0]);
            Ab[mt][1] = __float_as_uint(sXb[r0 + 8 * PAD]);
            Ab[mt][2] = __float_as_uint(sXb[r0 + 4]);
            Ab[mt][3] = __float_as_uint(sXb[r0 + 8 * PAD + 4]);
            Ar[mt][0] = __float_as_uint(sXr[r0]);
            Ar[mt][1] = __float_as_uint(sXr[r0 + 8 * PAD]);
            Ar[mt][2] = __float_as_uint(sXr[r0 + 4]);
            Ar[mt][3] = __float_as_uint(sXr[r0 + 8 * PAD + 4]);
        }
        #pragma unroll
        for (int nt = 0; nt < 2; nt++) {
            int c0 = (w * 16 + nt * 8 + g) * PAD + kb;
            Bb[nt][0] = __float_as_uint(sWb[c0]);
            Bb[nt][1] = __float_as_uint(sWb[c0 + 4]);
            Br[nt][0] = __float_as_uint(sWr[c0]);
            Br[nt][1] = __float_as_uint(sWr[c0 + 4]);
        }
        #pragma unroll
        for (int mt = 0; mt < 4; mt++)
            #pragma unroll
            for (int nt = 0; nt < 2; nt++) {
                mma_tf32(C[mt][nt], Ab[mt][0], Ab[mt][1], Ab[mt][2], Ab[mt][3],
                         Bb[nt][0], Bb[nt][1]);
                mma_tf32(C[mt][nt], Ar[mt][0], Ar[mt][1], Ar[mt][2], Ar[mt][3],
                         Bb[nt][0], Bb[nt][1]);
                mma_tf32(C[mt][nt], Ab[mt][0], Ab[mt][1], Ab[mt][2], Ab[mt][3],
                         Br[nt][0], Br[nt][1]);
            }
    }

    // ---- Epilogue: +b1, relu, dot w2 (per-thread 4 cols/row), quad reduce
    float b1p[2][2], w2p[2][2];
    #pragma unroll
    for (int nt = 0; nt < 2; nt++) {
        int col = w * 16 + nt * 8 + t4 * 2;
        float2 bb = *(const float2*)(b1 + (size_t)e * HID + col);
        float2 ww = *(const float2*)(W2 + (size_t)e * HID + col);
        b1p[nt][0] = bb.x; b1p[nt][1] = bb.y;
        w2p[nt][0] = ww.x; w2p[nt][1] = ww.y;
    }

    __syncthreads();   // all warps done reading smem; reuse sXb as reduction buffer
    float* red = sXb;  // red[m*8 + w], 512 floats

    #pragma unroll
    for (int mt = 0; mt < 4; mt++) {
        float s0 = 0.0f, s1 = 0.0f;
        #pragma unroll
        for (int nt = 0; nt < 2; nt++) {
            #pragma unroll
            for (int cc = 0; cc < 2; cc++) {
                float h0 = C[mt][nt][cc]     + b1p[nt][cc];
                float h1 = C[mt][nt][2 + cc] + b1p[nt][cc];
                h0 = h0 > 0.0f ? h0 : 0.0f;
                h1 = h1 > 0.0f ? h1 : 0.0f;
                s0 = fmaf(h0, w2p[nt][cc], s0);
                s1 = fmaf(h1, w2p[nt][cc], s1);
            }
        }
        // reduce over the 4 threads of the quad (t4 = 0..3)
        s0 += __shfl_xor_sync(0xFFFFFFFFu, s0, 1);
        s0 += __shfl_xor_sync(0xFFFFFFFFu, s0, 2);
        s1 += __shfl_xor_sync(0xFFFFFFFFu, s1, 1);
        s1 += __shfl_xor_sync(0xFFFFFFFFu, s1, 2);
        if (t4 == 0) {
            red[(mt * 16 + g) * 8 + w]     = s0;
            red[(mt * 16 + 8 + g) * 8 + w] = s1;
        }
    }
    __syncthreads();

    if (threadIdx.x < TILE_M) {
        int m = threadIdx.x;
        if (m < mvalid) {
            float s = 0.0f;
            #pragma unroll
            for (int q = 0; q < 8; q++) s += red[m * 8 + q];
            float y = s + b2[e];
            int gidx = g_bucket[base + m];
            out[gidx] = 1.0f / (1.0f + expf(-y));
        }
    }
}

// ---------------------------------------------------------------------------
extern "C" void kernel_launch(void* const* d_in, const int* in_sizes, int n_in,
                              void* d_out, int out_size) {
    const float* x     = (const float*)d_in[0];
    const int*   num32 = (const int*)d_in[1];
    const int*   c32   = (const int*)d_in[2];
    const float* W1    = (const float*)d_in[3];
    const float* b1    = (const float*)d_in[4];
    const float* W2    = (const float*)d_in[5];
    const float* b2    = (const float*)d_in[6];
    float*       out   = (float*)d_out;

    static bool attr_set = false;
    if (!attr_set) {
        cudaFuncSetAttribute(mlp_kernel,
                             cudaFuncAttributeMaxDynamicSharedMemorySize,
                             SMEM_BYTES);
        cudaFuncSetAttribute(mlp_kernel,
                             cudaFuncAttributePreferredSharedMemoryCarveout, 100);
        attr_set = true;
    }

    bin_kernel<<<NBLK, 256>>>(num32, c32);
    mlp_kernel<<<MAX_TILES, MLP_THREADS, SMEM_BYTES>>>(x, W1, b1, W2, b2, out);
}

// round 16
// speedup vs baseline: 1.8969x; 1.2763x over previous
#include <cuda_runtime.h>
#include <math.h>

// Problem constants
#define B      16384
#define IN     64
#define HID    128
#define E      64
#define NMAP   1000
#define TILE_M 64
#define NBLK   64                       // binning blocks (B/256)
#define MAX_TILES (B / TILE_M + E)      // 320
#define MLP_THREADS 256
#define PAD    68                        // X k-stride (A-frag bank = lane)
#define PADH   136                       // W h-stride (B-frag bank = 8*t4+g)

// SMEM layout (floats)
#define SXB_OFF 0
#define SXR_OFF (TILE_M * PAD)                    // 4352
#define SWB_OFF (2 * TILE_M * PAD)                // 8704
#define SWR_OFF (2 * TILE_M * PAD + IN * PADH)    // 17408
#define SMEM_FLOATS (2 * TILE_M * PAD + 2 * IN * PADH)   // 26112
#define SMEM_BYTES  (SMEM_FLOATS * 4)                     // 104448

// Scratch (device globals; no allocation allowed)
__device__ int g_e[B];
__device__ int g_hist[NBLK * E];        // per-block histogram rows
__device__ int g_expOff[E];
__device__ int g_counts[E];
__device__ int g_bucket[B];
__device__ int g_tileExpert[MAX_TILES];
__device__ int g_tileIdx[MAX_TILES];
__device__ int g_numTiles;
__device__ int g_bar1;                  // inter-phase arrive counter
__device__ int g_bar2;                  // completion counter (for reset)

// ---- tf32 helpers -----------------------------------------------------------
__device__ __forceinline__ unsigned f2tf32(float v) {
    unsigned u;
    asm("cvt.rna.tf32.f32 %0, %1;" : "=r"(u) : "f"(v));
    return u;
}
__device__ __forceinline__ float tf32big(float v) {
    return __uint_as_float(f2tf32(v));
}
// D += A(tf32) * B(tf32), m16n8k8, A row-major, B col-major
__device__ __forceinline__ void mma_tf32(float c[4],
                                         unsigned a0, unsigned a1, unsigned a2, unsigned a3,
                                         unsigned b0, unsigned b1) {
    asm("mma.sync.aligned.m16n8k8.row.col.f32.tf32.tf32.f32 "
        "{%0,%1,%2,%3}, {%4,%5,%6,%7}, {%8,%9}, {%0,%1,%2,%3};"
        : "+f"(c[0]), "+f"(c[1]), "+f"(c[2]), "+f"(c[3])
        : "r"(a0), "r"(a1), "r"(a2), "r"(a3), "r"(b0), "r"(b1));
}

// ---------------------------------------------------------------------------
// K1: fused binning. grid=64 x 256. Phase B scans a SMEM-staged hist matrix.
__global__ __launch_bounds__(256) void bin_kernel(const int* __restrict__ num32,
                                                  const int* __restrict__ c32) {
    __shared__ int sh[NBLK * E];        // 16KB staged histogram
    __shared__ int hs[E];
    __shared__ int s_stride;
    __shared__ int basev[E];
    __shared__ int s_wsum[2], s_wsum2[2];
    int t = threadIdx.x, b = blockIdx.x;
    int lane = t & 31, warp = t >> 5;

    // ---- Phase A: expert ids + per-block histogram
    if (t == 0) {
        int is64 = 1;
        for (int j = 1; j < 64; j += 2)
            if (c32[j] != 0) { is64 = 0; break; }
        s_stride = is64 ? 2 : 1;
    }
    if (t < E) hs[t] = 0;
    __syncthreads();
    int stride = s_stride;
    int i = b * 256 + t;
    int n = num32[(size_t)i * stride];
    n = n < 0 ? 0 : (n >= NMAP ? NMAP - 1 : n);
    int e = c32[(size_t)n * stride];
    e = e < 0 ? 0 : (e >= E ? E - 1 : e);
    g_e[i] = e;
    atomicAdd(&hs[e], 1);
    __syncthreads();
    if (t < E) g_hist[b * E + t] = hs[t];
    __threadfence();

    // ---- Device-wide barrier (64 CTAs all resident)
    if (t == 0) {
        atomicAdd(&g_bar1, 1);
        while (atomicAdd(&g_bar1, 0) < NBLK) { }
    }
    __syncthreads();

    // ---- Stage full hist matrix into SMEM (coalesced int4)
    {
        const int4* src = (const int4*)g_hist;
        int4* dst = (int4*)sh;
        #pragma unroll
        for (int j = t; j < (NBLK * E) / 4; j += 256)
            dst[j] = src[j];
    }
    __syncthreads();

    // ---- Phase B: scans (from SMEM) + scatter
    int tot = 0, pre = 0, exclC = 0, exclT = 0, nt = 0;
    if (t < E) {
        hs[t] = 0;   // reuse as local rank counter
        #pragma unroll
        for (int bb = 0; bb < NBLK; bb++) {
            int v = sh[bb * E + t];
            tot += v;
            if (bb < b) pre += v;
        }
        nt = (tot + TILE_M - 1) / TILE_M;
        int s1 = tot, s2 = nt;
        #pragma unroll
        for (int off = 1; off < 32; off <<= 1) {
            int n1 = __shfl_up_sync(0xFFFFFFFFu, s1, off);
            int n2 = __shfl_up_sync(0xFFFFFFFFu, s2, off);
            if (lane >= off) { s1 += n1; s2 += n2; }
        }
        exclC = s1 - tot;
        exclT = s2 - nt;
        if (lane == 31) { s_wsum[warp] = s1; s_wsum2[warp] = s2; }
    }
    __syncthreads();
    if (t < E) {
        int addC = (warp == 1) ? s_wsum[0]  : 0;
        int addT = (warp == 1) ? s_wsum2[0] : 0;
        int eOff = exclC + addC;
        basev[t] = eOff + pre;
        if (b == 0) {
            g_counts[t] = tot;
            g_expOff[t] = eOff;
            int t0 = exclT + addT;
            for (int j = 0; j < nt; j++) {
                g_tileExpert[t0 + j] = t;
                g_tileIdx[t0 + j]    = j;
            }
            if (t == E - 1) g_numTiles = t0 + nt;
        }
    }
    __syncthreads();
    int r = atomicAdd(&hs[e], 1);
    g_bucket[basev[e] + r] = i;

    // ---- Completion + deterministic counter reset for graph replay
    __syncthreads();
    if (t == 0) {
        int d = atomicAdd(&g_bar2, 1);
        if (d == NBLK - 1) { g_bar1 = 0; g_bar2 = 0; }
    }
}

// ---------------------------------------------------------------------------
// K2: per-tile fused MLP via tf32 mma.sync with 3xTF32 split.
// CTA = (expert, 64-sample tile), 256 threads (8 warps).
// Warp w owns hidden cols [w*16, w*16+16): 2 n-tiles of 8.
// W stored k-major: sW[k*136 + h] -> coalesced LDG.128 + conflict-free STS.128,
// B-fragment bank = 8*t4 + g (+const) = all 32 lanes distinct.
__global__ __launch_bounds__(MLP_THREADS) void mlp_kernel(
    const float* __restrict__ x,
    const float* __restrict__ W1,
    const float* __restrict__ b1,
    const float* __restrict__ W2,
    const float* __restrict__ b2,
    float* __restrict__ out)
{
    extern __shared__ float smem[];
    float* sXb = smem + SXB_OFF;
    float* sXr = smem + SXR_OFF;
    float* sWb = smem + SWB_OFF;
    float* sWr = smem + SWR_OFF;

    int tile = blockIdx.x;
    if (tile >= g_numTiles) return;

    int e    = g_tileExpert[tile];
    int ti   = g_tileIdx[tile];
    int cnt  = g_counts[e];
    int base = g_expOff[e] + ti * TILE_M;
    int mvalid = cnt - ti * TILE_M;
    if (mvalid > TILE_M) mvalid = TILE_M;

    // ---- Load + split W1[e], k-major: 8 x (LDG.128 + 2 STS.128) per thread
    {
        const float4* Wg = (const float4*)(W1 + (size_t)e * IN * HID);
        #pragma unroll
        for (int i = threadIdx.x; i < (IN * HID) / 4; i += MLP_THREADS) {
            int k  = i >> 5;            // 32 float4 per k-row
            int h4 = (i & 31) * 4;
            float4 v = Wg[i];
            float4 big, res;
            big.x = tf32big(v.x); res.x = tf32big(v.x - big.x);
            big.y = tf32big(v.y); res.y = tf32big(v.y - big.y);
            big.z = tf32big(v.z); res.z = tf32big(v.z - big.z);
            big.w = tf32big(v.w); res.w = tf32big(v.w - big.w);
            *(float4*)&sWb[k * PADH + h4] = big;
            *(float4*)&sWr[k * PADH + h4] = res;
        }
    }

    // ---- Load + split X tile: sX[m][k], 4 threads/row
    {
        int m  = threadIdx.x >> 2;               // 0..63
        int kq = (threadIdx.x & 3) * 16;
        int mc = m < mvalid ? m : (mvalid - 1);  // clamp (outputs guarded)
        int gidx = g_bucket[base + mc];
        const float4* xr = (const float4*)(x + (size_t)gidx * IN + kq);
        #pragma unroll
        for (int q = 0; q < 4; q++) {
            float4 v = xr[q];
            int k0 = kq + q * 4;
            float4 big, res;
            big.x = tf32big(v.x); res.x = tf32big(v.x - big.x);
            big.y = tf32big(v.y); res.y = tf32big(v.y - big.y);
            big.z = tf32big(v.z); res.z = tf32big(v.z - big.z);
            big.w = tf32big(v.w); res.w = tf32big(v.w - big.w);
            *(float4*)&sXb[m * PAD + k0] = big;
            *(float4*)&sXr[m * PAD + k0] = res;
        }
    }
    __syncthreads();

    int lane = threadIdx.x & 31;
    int w    = threadIdx.x >> 5;     // warp -> N block [w*16, w*16+16)
    int g    = lane >> 2;            // group id 0..7
    int t4   = lane & 3;             // thread in group 0..3

    float C[4][2][4];                // [mtile][ntile][frag]
    #pragma unroll
    for (int mt = 0; mt < 4; mt++)
        #pragma unroll
        for (int nt = 0; nt < 2; nt++)
            #pragma unroll
            for (int f = 0; f < 4; f++)
                C[mt][nt][f] = 0.0f;

    // ---- Mainloop: 8 k-steps; per step 40 frag loads + 24 MMAs per warp
    #pragma unroll
    for (int ks = 0; ks < 8; ks++) {
        unsigned Ab[4][4], Ar[4][4], Bb[2][2], Br[2][2];
        int kb = ks * 8 + t4;
        #pragma unroll
        for (int mt = 0; mt < 4; mt++) {
            int r0 = (mt * 16 + g) * PAD + kb;
            Ab[mt][0] = __float_as_uint(sXb[r0]);
            Ab[mt][1] = __float_as_uint(sXb[r0 + 8 * PAD]);
            Ab[mt][2] = __float_as_uint(sXb[r0 + 4]);
            Ab[mt][3] = __float_as_uint(sXb[r0 + 8 * PAD + 4]);
            Ar[mt][0] = __float_as_uint(sXr[r0]);
            Ar[mt][1] = __float_as_uint(sXr[r0 + 8 * PAD]);
            Ar[mt][2] = __float_as_uint(sXr[r0 + 4]);
            Ar[mt][3] = __float_as_uint(sXr[r0 + 8 * PAD + 4]);
        }
        #pragma unroll
        for (int nt = 0; nt < 2; nt++) {
            int col = w * 16 + nt * 8 + g;
            Bb[nt][0] = __float_as_uint(sWb[kb * PADH + col]);
            Bb[nt][1] = __float_as_uint(sWb[(kb + 4) * PADH + col]);
            Br[nt][0] = __float_as_uint(sWr[kb * PADH + col]);
            Br[nt][1] = __float_as_uint(sWr[(kb + 4) * PADH + col]);
        }
        #pragma unroll
        for (int mt = 0; mt < 4; mt++)
            #pragma unroll
            for (int nt = 0; nt < 2; nt++) {
                mma_tf32(C[mt][nt], Ab[mt][0], Ab[mt][1], Ab[mt][2], Ab[mt][3],
                         Bb[nt][0], Bb[nt][1]);
                mma_tf32(C[mt][nt], Ar[mt][0], Ar[mt][1], Ar[mt][2], Ar[mt][3],
                         Bb[nt][0], Bb[nt][1]);
                mma_tf32(C[mt][nt], Ab[mt][0], Ab[mt][1], Ab[mt][2], Ab[mt][3],
                         Br[nt][0], Br[nt][1]);
            }
    }

    // ---- Epilogue: +b1, relu, dot w2 (per-thread cols), quad reduce
    float b1p[2][2], w2p[2][2];
    #pragma unroll
    for (int nt = 0; nt < 2; nt++) {
        int col = w * 16 + nt * 8 + t4 * 2;
        float2 bb = *(const float2*)(b1 + (size_t)e * HID + col);
        float2 ww = *(const float2*)(W2 + (size_t)e * HID + col);
        b1p[nt][0] = bb.x; b1p[nt][1] = bb.y;
        w2p[nt][0] = ww.x; w2p[nt][1] = ww.y;
    }

    __syncthreads();   // all warps done reading smem; reuse sXb as reduction buffer
    float* red = sXb;  // red[m*8 + w], 512 floats

    #pragma unroll
    for (int mt = 0; mt < 4; mt++) {
        float s0 = 0.0f, s1 = 0.0f;
        #pragma unroll
        for (int nt = 0; nt < 2; nt++) {
            #pragma unroll
            for (int cc = 0; cc < 2; cc++) {
                float h0 = C[mt][nt][cc]     + b1p[nt][cc];
                float h1 = C[mt][nt][2 + cc] + b1p[nt][cc];
                h0 = h0 > 0.0f ? h0 : 0.0f;
                h1 = h1 > 0.0f ? h1 : 0.0f;
                s0 = fmaf(h0, w2p[nt][cc], s0);
                s1 = fmaf(h1, w2p[nt][cc], s1);
            }
        }
        s0 += __shfl_xor_sync(0xFFFFFFFFu, s0, 1);
        s0 += __shfl_xor_sync(0xFFFFFFFFu, s0, 2);
        s1 += __shfl_xor_sync(0xFFFFFFFFu, s1, 1);
        s1 += __shfl_xor_sync(0xFFFFFFFFu, s1, 2);
        if (t4 == 0) {
            red[(mt * 16 + g) * 8 + w]     = s0;
            red[(mt * 16 + 8 + g) * 8 + w] = s1;
        }
    }
    __syncthreads();

    if (threadIdx.x < TILE_M) {
        int m = threadIdx.x;
        if (m < mvalid) {
            float s = 0.0f;
            #pragma unroll
            for (int q = 0; q < 8; q++) s += red[m * 8 + q];
            float y = s + b2[e];
            int gidx = g_bucket[base + m];
            out[gidx] = 1.0f / (1.0f + expf(-y));
        }
    }
}

// ---------------------------------------------------------------------------
extern "C" void kernel_launch(void* const* d_in, const int* in_sizes, int n_in,
                              void* d_out, int out_size) {
    const float* x     = (const float*)d_in[0];
    const int*   num32 = (const int*)d_in[1];
    const int*   c32   = (const int*)d_in[2];
    const float* W1    = (const float*)d_in[3];
    const float* b1    = (const float*)d_in[4];
    const float* W2    = (const float*)d_in[5];
    const float* b2    = (const float*)d_in[6];
    float*       out   = (float*)d_out;

    static bool attr_set = false;
    if (!attr_set) {
        cudaFuncSetAttribute(mlp_kernel,
                             cudaFuncAttributeMaxDynamicSharedMemorySize,
                             SMEM_BYTES);
        cudaFuncSetAttribute(mlp_kernel,
                             cudaFuncAttributePreferredSharedMemoryCarveout, 100);
        attr_set = true;
    }

    bin_kernel<<<NBLK, 256>>>(num32, c32);
    mlp_kernel<<<MAX_TILES, MLP_THREADS, SMEM_BYTES>>>(x, W1, b1, W2, b2, out);
}